// round 15
// baseline (speedup 1.0000x reference)
#include <cuda_runtime.h>
#include <cuda_fp16.h>
#include <cstdint>

// ============================================================================
// cosine_layer: out[b,o] = dot(x[b,:], w[:,o]) / (max(||x_b||,eps)*max(||w_o||,eps))
//   x: [4096,4096] f32, w: [4096,32768] f32, out: [4096,32768] f32
//
// sm_103 base target (no tcgen05 -- virtual arch is compute_103). Strategy:
//   1) prep: x -> fp16 SW128-swizzled K-major 64-k images + row partial sumsq
//      (SMEM-staged, linear coalesced gmem writes -- R14 win)
//   2) prep: w -> fp16*2^12 transposed [N,K] images + col partial sumsq (same)
//   3) norms reduced deterministically; 2^12 folded into invw
//   4) GEMM: R9 inner body (best measured; R10/R12/R13 perturbations all
//      regressed), now PERSISTENT: grid = #SMs, each CTA walks tiles
//      ct, ct+grid, ... The double-buffer pipeline crosses tile boundaries
//      (last chunk of tile i prefetches tile i+1's chunk 0), so the per-CTA
//      epilogue+prologue stall (~3100 cyc x ~27 transitions ~ 50 us) is
//      overlapped instead of serialized.
// Launch order (4 launches; profiled launch = seq index 3 = gemm).
// ============================================================================

namespace {
constexpr int M_DIM = 4096;
constexpr int N_DIM = 32768;
constexpr int K_DIM = 4096;

constexpr int BM = 128;
constexpr int BN = 256;
constexpr int BK = 64;            // prep image K-granularity
constexpr int KT = K_DIM / BK;    // 64 images
constexpr int MT = M_DIM / BM;    // 32
constexpr int NT = N_DIM / BN;    // 128
constexpr int NTILES = MT * NT;   // 4096

constexpr int A_IMG = BM * BK * 2;         // 16384 B per 64-k A image
constexpr int B_IMG = BN * BK * 2;         // 32768 B per 64-k B image
constexpr int IMGS_PER_STAGE = 2;          // chunk = 128 k
constexpr int KT2 = KT / IMGS_PER_STAGE;   // 32 chunks per tile
constexpr int STAGE_B = IMGS_PER_STAGE * (A_IMG + B_IMG);  // 98304 B
constexpr int STAGES = 2;
constexpr int SMEM_TOTAL = STAGES * STAGE_B;               // 196608 B

constexpr float WSCALE = 4096.0f;   // 2^12, cancels in cosine (folded into invw)
constexpr float EPSN = 1e-8f;
}  // namespace

// ---------------------------------------------------------------------------
// Device scratch (static device globals -- allocation-free)
// ---------------------------------------------------------------------------
__device__ __align__(1024) __half g_xh[(size_t)M_DIM * K_DIM];   // 32 MB
__device__ __align__(1024) __half g_wh[(size_t)N_DIM * K_DIM];   // 256 MB
__device__ float g_xpart[KT * M_DIM];
__device__ float g_wpart[KT * N_DIM];
__device__ float g_invx[M_DIM];
__device__ float g_invw[N_DIM];

// ---------------------------------------------------------------------------
// helpers
// ---------------------------------------------------------------------------
__device__ __forceinline__ uint32_t smem_u32(const void* p) {
    uint32_t a;
    asm("{ .reg .u64 t; cvta.to.shared.u64 t, %1; cvt.u32.u64 %0, t; }"
        : "=r"(a) : "l"(p));
    return a;
}

__device__ __forceinline__ uint32_t swz128(uint32_t off) {
    return off ^ ((off >> 3) & 0x70);
}

#define CP16(saddr, gptr)                                                     \
    asm volatile("cp.async.cg.shared.global [%0], [%1], 16;"                  \
                 :: "r"(saddr), "l"(gptr) : "memory")

#define CP_COMMIT() asm volatile("cp.async.commit_group;" ::: "memory")

#define LDSM4(d0, d1, d2, d3, addr)                                           \
    asm volatile("ldmatrix.sync.aligned.m8n8.x4.shared.b16 {%0,%1,%2,%3}, [%4];" \
                 : "=r"(d0), "=r"(d1), "=r"(d2), "=r"(d3) : "r"(addr))

__device__ __forceinline__ void mma16816(float* d, const uint32_t* a,
                                         const uint32_t* b) {
    asm volatile(
        "mma.sync.aligned.m16n8k16.row.col.f32.f16.f16.f32 "
        "{%0,%1,%2,%3}, {%4,%5,%6,%7}, {%8,%9}, {%0,%1,%2,%3};"
        : "+f"(d[0]), "+f"(d[1]), "+f"(d[2]), "+f"(d[3])
        : "r"(a[0]), "r"(a[1]), "r"(a[2]), "r"(a[3]), "r"(b[0]), "r"(b[1]));
}

// ---------------------------------------------------------------------------
// Prep: x -> fp16 swizzled images + row partial sumsq. grid (MT,KT), 128 thr.
// SMEM-staged: swizzled stores to smem (conflict-free), linear copy to gmem.
// ---------------------------------------------------------------------------
__global__ void cos_conv_x(const float* __restrict__ x) {
    __shared__ __align__(16) char simg[A_IMG];   // 16 KB
    const int mt = blockIdx.x, kt = blockIdx.y, t = threadIdx.x;
    const int m = mt * BM + t;
    const float4* src =
        reinterpret_cast<const float4*>(x + (size_t)m * K_DIM + kt * BK);
    float s = 0.0f;
    uint32_t h[32];
#pragma unroll
    for (int i = 0; i < 16; i++) {
        float4 v = src[i];
        s += v.x * v.x + v.y * v.y + v.z * v.z + v.w * v.w;
        __half2 p0 = __floats2half2_rn(v.x, v.y);
        __half2 p1 = __floats2half2_rn(v.z, v.w);
        h[2 * i]     = *reinterpret_cast<uint32_t*>(&p0);
        h[2 * i + 1] = *reinterpret_cast<uint32_t*>(&p1);
    }
    const uint4* hv = reinterpret_cast<const uint4*>(h);
#pragma unroll
    for (int j = 0; j < 8; j++) {
        uint32_t off = swz128((uint32_t)(t * 128 + j * 16));
        *reinterpret_cast<uint4*>(simg + off) = hv[j];
    }
    g_xpart[kt * M_DIM + m] = s;
    __syncthreads();

    uint4* dst = reinterpret_cast<uint4*>(
        reinterpret_cast<char*>(g_xh) + (size_t)(mt * KT + kt) * A_IMG);
    const uint4* s4 = reinterpret_cast<const uint4*>(simg);
#pragma unroll
    for (int i = 0; i < A_IMG / 16 / BM; i++)
        dst[t + i * BM] = s4[t + i * BM];
}

// ---------------------------------------------------------------------------
// Prep: w -> fp16*2^12 transposed [N,K] images + col partial sumsq.
// grid (NT,KT), 256 thr. SMEM-staged like conv_x.
// ---------------------------------------------------------------------------
__global__ void cos_conv_w(const float* __restrict__ w) {
    __shared__ __align__(16) char simg[B_IMG];   // 32 KB
    const int nt = blockIdx.x, kt = blockIdx.y, t = threadIdx.x;
    const int n = nt * BN + t;
    const float* base = w + (size_t)(kt * BK) * N_DIM + n;
    float s = 0.0f;
    uint32_t h[32];
#pragma unroll
    for (int j = 0; j < 32; j++) {
        float a = base[(size_t)(2 * j) * N_DIM];
        float b = base[(size_t)(2 * j + 1) * N_DIM];
        s += a * a + b * b;
        __half2 p = __floats2half2_rn(a * WSCALE, b * WSCALE);
        h[j] = *reinterpret_cast<uint32_t*>(&p);
    }
    const uint4* hv = reinterpret_cast<const uint4*>(h);
#pragma unroll
    for (int j = 0; j < 8; j++) {
        uint32_t off = swz128((uint32_t)(t * 128 + j * 16));
        *reinterpret_cast<uint4*>(simg + off) = hv[j];
    }
    g_wpart[kt * N_DIM + n] = s;
    __syncthreads();

    uint4* dst = reinterpret_cast<uint4*>(
        reinterpret_cast<char*>(g_wh) + (size_t)(nt * KT + kt) * B_IMG);
    const uint4* s4 = reinterpret_cast<const uint4*>(simg);
#pragma unroll
    for (int i = 0; i < B_IMG / 16 / BN; i++)
        dst[t + i * BN] = s4[t + i * BN];
}

// Combined norm reduction (x rows then w cols), one launch, deterministic.
__global__ void cos_norms() {
    const int gidx = blockIdx.x * blockDim.x + threadIdx.x;
    if (gidx < M_DIM) {
        const int m = gidx;
        float s = 0.0f;
#pragma unroll 8
        for (int kt = 0; kt < KT; kt++) s += g_xpart[kt * M_DIM + m];
        g_invx[m] = 1.0f / fmaxf(sqrtf(s), EPSN);
    } else {
        const int n = gidx - M_DIM;
        float s = 0.0f;
#pragma unroll 8
        for (int kt = 0; kt < KT; kt++) s += g_wpart[kt * N_DIM + n];
        g_invw[n] = 1.0f / (fmaxf(sqrtf(s), EPSN) * WSCALE);
    }
}

// ---------------------------------------------------------------------------
// GEMM: persistent CTAs, R9 inner body. mma.sync m16n8k16, CTA tile 128x256,
// 8 warps (warp 64x64). Double-buffered 128-k chunks; refill parts after
// ks0/ks1/ks2 of image h=0, commit after ks3. The pipeline crosses tile
// boundaries: the last chunk of a tile prefetches the next tile's chunk 0.
// Tile order: tile = mt + 32*nt, CTA ct handles ct, ct+grid, ... (mt-fast,
// same L2 pattern as the old (MT, NT) grid).
// Stage smem layout: [A img0][A img1][B img0][B img1]
// ---------------------------------------------------------------------------
// part 0: both A images (8x CP16); part 1: B bytes [0,32K) ; part 2: B [32K,64K)
__device__ __forceinline__ void refill_part(uint32_t sbase, int slot,
                                            const char* gA, const char* gB,
                                            int t, int part) {
    const uint32_t sA = sbase + slot * STAGE_B;
    const uint32_t sB = sA + IMGS_PER_STAGE * A_IMG;
    if (part == 0) {
#pragma unroll
        for (int i = 0; i < 8; i++)
            CP16(sA + (uint32_t)(t + i * 256) * 16,
                 gA + (size_t)(t + i * 256) * 16);
    } else if (part == 1) {
#pragma unroll
        for (int i = 0; i < 8; i++)
            CP16(sB + (uint32_t)(t + i * 256) * 16,
                 gB + (size_t)(t + i * 256) * 16);
    } else {
#pragma unroll
        for (int i = 8; i < 16; i++)
            CP16(sB + (uint32_t)(t + i * 256) * 16,
                 gB + (size_t)(t + i * 256) * 16);
    }
}

__device__ __forceinline__ const char* tileA(int tile) {
    return reinterpret_cast<const char*>(g_xh) +
           (size_t)((tile & (MT - 1)) * KT) * A_IMG;
}
__device__ __forceinline__ const char* tileB(int tile) {
    return reinterpret_cast<const char*>(g_wh) +
           (size_t)((tile >> 5) * KT) * B_IMG;
}

__global__ void __launch_bounds__(256, 1) cos_gemm(float* __restrict__ out) {
    extern __shared__ char smem[];
    const uint32_t sbase = smem_u32(smem);
    const int tid = threadIdx.x;
    const int wid = tid >> 5;
    const int lid = tid & 31;
    const int ct = blockIdx.x;
    const int gsz = gridDim.x;

    const int wm = wid & 1;   // m 64-block within CTA
    const int wn = wid >> 1;  // n 64-block within CTA

    // ldmatrix lane address precompute (SW128 swizzle linearized):
    // addr = row*128 + ((ks*32 | kg) ^ ((row&7)<<4))
    const int r = lid & 7, g = lid >> 3;
    const int rA = wm * 64 + (g & 1) * 8 + r;          // + i*16 per m-tile
    const uint32_t kgA = (uint32_t)(g >> 1) << 4;
    const uint32_t sxA = (uint32_t)(rA & 7) << 4;
    const int rB = wn * 64 + ((g >> 1) & 1) * 8 + r;   // + p*16 per n-pair
    const uint32_t kgB = (uint32_t)(g & 1) << 4;
    const uint32_t sxB = (uint32_t)(rB & 7) << 4;

    const int qr = lid >> 2;
    const int qc = (lid & 3) * 2;

    if (ct >= NTILES) return;

    // prologue: first tile's chunk 0 into slot 0
    {
        const char* pA = tileA(ct);
        const char* pB = tileB(ct);
        refill_part(sbase, 0, pA, pB, tid, 0);
        refill_part(sbase, 0, pA, pB, tid, 1);
        refill_part(sbase, 0, pA, pB, tid, 2);
        CP_COMMIT();
    }

    int slot = 0;
    for (int tile = ct; tile < NTILES; tile += gsz) {
        const int mt = tile & (MT - 1);
        const int nt = tile >> 5;
        const char* gA = tileA(tile);
        const char* gB = tileB(tile);
        const int ntile = tile + gsz;             // next tile (may be >= NTILES)

        float acc[4][8][4];
#pragma unroll
        for (int i = 0; i < 4; i++)
#pragma unroll
            for (int j = 0; j < 8; j++)
#pragma unroll
                for (int c = 0; c < 4; c++) acc[i][j][c] = 0.0f;

        for (int it = 0; it < KT2; ++it) {
            // All outstanding cp.async groups complete => chunk `it` resident.
            asm volatile("cp.async.wait_group 0;" ::: "memory");
            __syncthreads();
            // After this barrier, slot^1's readers (previous chunk) are all
            // done, so slot^1 refill may be issued during h=0 below.

            const uint32_t st = sbase + slot * STAGE_B;

            // Next chunk: same tile's it+1, or next tile's chunk 0.
            const char *nA, *nB;
            bool do_refill = true;
            if (it + 1 < KT2) {
                nA = gA + (size_t)(it + 1) * IMGS_PER_STAGE * A_IMG;
                nB = gB + (size_t)(it + 1) * IMGS_PER_STAGE * B_IMG;
            } else if (ntile < NTILES) {
                nA = tileA(ntile);
                nB = tileB(ntile);
            } else {
                do_refill = false;
                nA = gA;
                nB = gB;
            }

#pragma unroll
            for (int h = 0; h < IMGS_PER_STAGE; h++) {
                const uint32_t stA = st + (uint32_t)h * A_IMG;
                const uint32_t stB =
                    st + IMGS_PER_STAGE * A_IMG + (uint32_t)h * B_IMG;
#pragma unroll
                for (int ks = 0; ks < 4; ks++) {
                    const uint32_t kb = (uint32_t)ks << 5;
                    uint32_t a[4][4], b[8][2];
#pragma unroll
                    for (int i = 0; i < 4; i++) {
                        uint32_t ad = stA + (uint32_t)((rA + i * 16) * 128) +
                                      ((kb | kgA) ^ sxA);
                        LDSM4(a[i][0], a[i][1], a[i][2], a[i][3], ad);
                    }
#pragma unroll
                    for (int p = 0; p < 4; p++) {
                        uint32_t ad = stB + (uint32_t)((rB + p * 16) * 128) +
                                      ((kb | kgB) ^ sxB);
                        LDSM4(b[2 * p][0], b[2 * p][1], b[2 * p + 1][0],
                              b[2 * p + 1][1], ad);
                    }
#pragma unroll
                    for (int i = 0; i < 4; i++)
#pragma unroll
                        for (int j = 0; j < 8; j++)
                            mma16816(acc[i][j], a[i], b[j]);

                    // R9 schedule: part0@ks0, part1@ks1, part2@ks2, commit@ks3.
                    if (h == 0) {
                        if (ks < 3) {
                            if (do_refill)
                                refill_part(sbase, slot ^ 1, nA, nB, tid, ks);
                        } else {
                            CP_COMMIT();   // one group per chunk (may be empty)
                        }
                    }
                }
            }

            slot ^= 1;
        }

        // ---- per-tile epilogue: runs while the next tile's chunk 0 is in
        //      flight (committed during the last chunk's h=0). ----
        const int mbase = mt * BM + wm * 64;
        const int nbase = nt * BN + wn * 64;
#pragma unroll
        for (int i = 0; i < 4; i++) {
            const int m0 = mbase + i * 16 + qr;
            const float ix0 = g_invx[m0];
            const float ix1 = g_invx[m0 + 8];
            float* row0 = out + (size_t)m0 * N_DIM + nbase;
            float* row1 = row0 + (size_t)8 * N_DIM;
#pragma unroll
            for (int j = 0; j < 8; j++) {
                const int nn = j * 8 + qc;
                const float iw0 = g_invw[nbase + nn];
                const float iw1 = g_invw[nbase + nn + 1];
                float2 v0, v1;
                v0.x = acc[i][j][0] * ix0 * iw0;
                v0.y = acc[i][j][1] * ix0 * iw1;
                v1.x = acc[i][j][2] * ix1 * iw0;
                v1.y = acc[i][j][3] * ix1 * iw1;
                *reinterpret_cast<float2*>(row0 + nn) = v0;
                *reinterpret_cast<float2*>(row1 + nn) = v1;
            }
        }
    }
}

// ---------------------------------------------------------------------------
// kernel_launch
// ---------------------------------------------------------------------------
extern "C" void kernel_launch(void* const* d_in, const int* in_sizes, int n_in,
                              void* d_out, int out_size) {
    (void)in_sizes; (void)n_in; (void)out_size;
    const float* x = (const float*)d_in[0];
    const float* w = (const float*)d_in[1];
    float* out = (float*)d_out;

    cos_conv_x<<<dim3(MT, KT), BM>>>(x);
    cos_conv_w<<<dim3(NT, KT), BN>>>(w);
    cos_norms<<<(M_DIM + N_DIM) / 256, 256>>>();

    int nsm = 148;
    cudaDeviceGetAttribute(&nsm, cudaDevAttrMultiProcessorCount, 0);
    cudaFuncSetAttribute(cos_gemm, cudaFuncAttributeMaxDynamicSharedMemorySize,
                         SMEM_TOTAL);
    cos_gemm<<<nsm, 256, SMEM_TOTAL>>>(out);
}

// round 16
// speedup vs baseline: 1.0290x; 1.0290x over previous
#include <cuda_runtime.h>
#include <cuda_fp16.h>
#include <cstdint>

// ============================================================================
// cosine_layer: out[b,o] = dot(x[b,:], w[:,o]) / (max(||x_b||,eps)*max(||w_o||,eps))
//   x: [4096,4096] f32, w: [4096,32768] f32, out: [4096,32768] f32
//
// sm_103 base target (no tcgen05). Strategy:
//   1) prep: x -> fp16 SW128-swizzled K-major 64-k images + row partial sumsq
//      (SMEM-staged, linear coalesced writes -- R14)
//   2) prep: w -> fp16*2^12 transposed [N,K] images + col partial sumsq (same)
//   3) norms reduced deterministically; 2^12 folded into invw
//   4) GEMM: NEW 2-CTA/SM shape. CTA = 128 threads (4 warps), tile 128x128,
//      warp tile 64x64 (identical inner body shape to the proven R9 kernel:
//      8 LDSM + 32 HMMA per k16-step, ~214 regs). Stage = one 64-k image
//      pair (32 KB), double-buffered (64 KB/CTA) -> 2 CTAs/SM, so one CTA's
//      wait/barrier bubbles are covered by the sibling CTA's HMMAs.
//      B's 128-wide subtile is a contiguous 16 KB half of the 256-wide prep
//      image, so prep layout is unchanged.
// Launch order (4 launches; profiled launch = seq index 3 = gemm).
// ============================================================================

namespace {
constexpr int M_DIM = 4096;
constexpr int N_DIM = 32768;
constexpr int K_DIM = 4096;

constexpr int BM = 128;
constexpr int BN = 256;           // prep B image width (unchanged)
constexpr int BK = 64;            // prep image K-granularity
constexpr int KT = K_DIM / BK;    // 64 images
constexpr int MT = M_DIM / BM;    // 32
constexpr int NT = N_DIM / BN;    // 128 (prep grid)
constexpr int NT2 = N_DIM / 128;  // 256 (gemm tile columns)

constexpr int A_IMG = BM * BK * 2;         // 16384 B per 64-k A image
constexpr int B_IMG = BN * BK * 2;         // 32768 B per 64-k B image (256-wide)
constexpr int B_HALF = 16384;              // 128-wide subtile: contiguous half

// GEMM stage: [A 16KB][B half 16KB] = 32 KB; double buffered
constexpr int STAGE2 = A_IMG + B_HALF;     // 32768
constexpr int SMEM_G = 2 * STAGE2;         // 65536 per CTA -> 2 CTAs/SM

constexpr float WSCALE = 4096.0f;   // 2^12, cancels in cosine (folded into invw)
constexpr float EPSN = 1e-8f;
}  // namespace

// ---------------------------------------------------------------------------
// Device scratch (static device globals -- allocation-free)
// ---------------------------------------------------------------------------
__device__ __align__(1024) __half g_xh[(size_t)M_DIM * K_DIM];   // 32 MB
__device__ __align__(1024) __half g_wh[(size_t)N_DIM * K_DIM];   // 256 MB
__device__ float g_xpart[KT * M_DIM];
__device__ float g_wpart[KT * N_DIM];
__device__ float g_invx[M_DIM];
__device__ float g_invw[N_DIM];

// ---------------------------------------------------------------------------
// helpers
// ---------------------------------------------------------------------------
__device__ __forceinline__ uint32_t smem_u32(const void* p) {
    uint32_t a;
    asm("{ .reg .u64 t; cvta.to.shared.u64 t, %1; cvt.u32.u64 %0, t; }"
        : "=r"(a) : "l"(p));
    return a;
}

__device__ __forceinline__ uint32_t swz128(uint32_t off) {
    return off ^ ((off >> 3) & 0x70);
}

#define CP16(saddr, gptr)                                                     \
    asm volatile("cp.async.cg.shared.global [%0], [%1], 16;"                  \
                 :: "r"(saddr), "l"(gptr) : "memory")

#define CP_COMMIT() asm volatile("cp.async.commit_group;" ::: "memory")

#define LDSM4(d0, d1, d2, d3, addr)                                           \
    asm volatile("ldmatrix.sync.aligned.m8n8.x4.shared.b16 {%0,%1,%2,%3}, [%4];" \
                 : "=r"(d0), "=r"(d1), "=r"(d2), "=r"(d3) : "r"(addr))

__device__ __forceinline__ void mma16816(float* d, const uint32_t* a,
                                         const uint32_t* b) {
    asm volatile(
        "mma.sync.aligned.m16n8k16.row.col.f32.f16.f16.f32 "
        "{%0,%1,%2,%3}, {%4,%5,%6,%7}, {%8,%9}, {%0,%1,%2,%3};"
        : "+f"(d[0]), "+f"(d[1]), "+f"(d[2]), "+f"(d[3])
        : "r"(a[0]), "r"(a[1]), "r"(a[2]), "r"(a[3]), "r"(b[0]), "r"(b[1]));
}

// ---------------------------------------------------------------------------
// Prep: x -> fp16 swizzled images + row partial sumsq. grid (MT,KT), 128 thr.
// SMEM-staged: swizzled stores to smem (conflict-free), linear copy to gmem.
// ---------------------------------------------------------------------------
__global__ void cos_conv_x(const float* __restrict__ x) {
    __shared__ __align__(16) char simg[A_IMG];   // 16 KB
    const int mt = blockIdx.x, kt = blockIdx.y, t = threadIdx.x;
    const int m = mt * BM + t;
    const float4* src =
        reinterpret_cast<const float4*>(x + (size_t)m * K_DIM + kt * BK);
    float s = 0.0f;
    uint32_t h[32];
#pragma unroll
    for (int i = 0; i < 16; i++) {
        float4 v = src[i];
        s += v.x * v.x + v.y * v.y + v.z * v.z + v.w * v.w;
        __half2 p0 = __floats2half2_rn(v.x, v.y);
        __half2 p1 = __floats2half2_rn(v.z, v.w);
        h[2 * i]     = *reinterpret_cast<uint32_t*>(&p0);
        h[2 * i + 1] = *reinterpret_cast<uint32_t*>(&p1);
    }
    const uint4* hv = reinterpret_cast<const uint4*>(h);
#pragma unroll
    for (int j = 0; j < 8; j++) {
        uint32_t off = swz128((uint32_t)(t * 128 + j * 16));
        *reinterpret_cast<uint4*>(simg + off) = hv[j];
    }
    g_xpart[kt * M_DIM + m] = s;
    __syncthreads();

    uint4* dst = reinterpret_cast<uint4*>(
        reinterpret_cast<char*>(g_xh) + (size_t)(mt * KT + kt) * A_IMG);
    const uint4* s4 = reinterpret_cast<const uint4*>(simg);
#pragma unroll
    for (int i = 0; i < A_IMG / 16 / BM; i++)
        dst[t + i * BM] = s4[t + i * BM];
}

// ---------------------------------------------------------------------------
// Prep: w -> fp16*2^12 transposed [N,K] images + col partial sumsq.
// grid (NT,KT), 256 thr. SMEM-staged like conv_x.
// ---------------------------------------------------------------------------
__global__ void cos_conv_w(const float* __restrict__ w) {
    __shared__ __align__(16) char simg[B_IMG];   // 32 KB
    const int nt = blockIdx.x, kt = blockIdx.y, t = threadIdx.x;
    const int n = nt * BN + t;
    const float* base = w + (size_t)(kt * BK) * N_DIM + n;
    float s = 0.0f;
    uint32_t h[32];
#pragma unroll
    for (int j = 0; j < 32; j++) {
        float a = base[(size_t)(2 * j) * N_DIM];
        float b = base[(size_t)(2 * j + 1) * N_DIM];
        s += a * a + b * b;
        __half2 p = __floats2half2_rn(a * WSCALE, b * WSCALE);
        h[j] = *reinterpret_cast<uint32_t*>(&p);
    }
    const uint4* hv = reinterpret_cast<const uint4*>(h);
#pragma unroll
    for (int j = 0; j < 8; j++) {
        uint32_t off = swz128((uint32_t)(t * 128 + j * 16));
        *reinterpret_cast<uint4*>(simg + off) = hv[j];
    }
    g_wpart[kt * N_DIM + n] = s;
    __syncthreads();

    uint4* dst = reinterpret_cast<uint4*>(
        reinterpret_cast<char*>(g_wh) + (size_t)(nt * KT + kt) * B_IMG);
    const uint4* s4 = reinterpret_cast<const uint4*>(simg);
#pragma unroll
    for (int i = 0; i < B_IMG / 16 / BN; i++)
        dst[t + i * BN] = s4[t + i * BN];
}

// Combined norm reduction (x rows then w cols), one launch, deterministic.
__global__ void cos_norms() {
    const int gidx = blockIdx.x * blockDim.x + threadIdx.x;
    if (gidx < M_DIM) {
        const int m = gidx;
        float s = 0.0f;
#pragma unroll 8
        for (int kt = 0; kt < KT; kt++) s += g_xpart[kt * M_DIM + m];
        g_invx[m] = 1.0f / fmaxf(sqrtf(s), EPSN);
    } else {
        const int n = gidx - M_DIM;
        float s = 0.0f;
#pragma unroll 8
        for (int kt = 0; kt < KT; kt++) s += g_wpart[kt * N_DIM + n];
        g_invw[n] = 1.0f / (fmaxf(sqrtf(s), EPSN) * WSCALE);
    }
}

// ---------------------------------------------------------------------------
// GEMM: 2 CTAs/SM. CTA 128 threads (4 warps), tile 128x128, warp tile 64x64.
// Stage = [A img 16KB][B half 16KB]; double-buffered 64-k chunks.
// Refill: A-next @ks0, B-next @ks1, commit @ks3 (R9-style late placement).
// grid (MT, NT2), mt fast for L2 reuse of B.
// ---------------------------------------------------------------------------
__device__ __forceinline__ void refA(uint32_t sbase, int slot, const char* gA,
                                     int t) {
    const uint32_t sA = sbase + slot * STAGE2;
#pragma unroll
    for (int i = 0; i < 8; i++)
        CP16(sA + (uint32_t)(t + i * 128) * 16, gA + (size_t)(t + i * 128) * 16);
}
__device__ __forceinline__ void refB(uint32_t sbase, int slot, const char* gB,
                                     int t) {
    const uint32_t sB = sbase + slot * STAGE2 + A_IMG;
#pragma unroll
    for (int i = 0; i < 8; i++)
        CP16(sB + (uint32_t)(t + i * 128) * 16, gB + (size_t)(t + i * 128) * 16);
}

__global__ void __launch_bounds__(128, 2) cos_gemm(float* __restrict__ out) {
    extern __shared__ char smem[];
    const uint32_t sbase = smem_u32(smem);
    const int tid = threadIdx.x;
    const int wid = tid >> 5;
    const int lid = tid & 31;
    const int mt = blockIdx.x;
    const int nt2 = blockIdx.y;

    const int wm = wid & 1;   // m 64-block within CTA
    const int wn = wid >> 1;  // n 64-block within CTA

    // ldmatrix lane address precompute (SW128 swizzle linearized):
    // addr = row*128 + ((ks*32 | kg) ^ ((row&7)<<4))
    const int r = lid & 7, g = lid >> 3;
    const int rA = wm * 64 + (g & 1) * 8 + r;          // + i*16 per m-tile
    const uint32_t kgA = (uint32_t)(g >> 1) << 4;
    const uint32_t sxA = (uint32_t)(rA & 7) << 4;
    const int rB = wn * 64 + ((g >> 1) & 1) * 8 + r;   // + p*16 per n-pair
    const uint32_t kgB = (uint32_t)(g & 1) << 4;
    const uint32_t sxB = (uint32_t)(rB & 7) << 4;

    const char* gA = reinterpret_cast<const char*>(g_xh) + (size_t)(mt * KT) * A_IMG;
    // 128-wide B subtile: contiguous 16KB half of the 256-wide prep image.
    const char* gB = reinterpret_cast<const char*>(g_wh) +
                     (size_t)((nt2 >> 1) * KT) * B_IMG + (size_t)(nt2 & 1) * B_HALF;

    float acc[4][8][4];
#pragma unroll
    for (int i = 0; i < 4; i++)
#pragma unroll
        for (int j = 0; j < 8; j++)
#pragma unroll
            for (int c = 0; c < 4; c++) acc[i][j][c] = 0.0f;

    // prologue: image 0 into slot 0
    refA(sbase, 0, gA, tid);
    refB(sbase, 0, gB, tid);
    CP_COMMIT();

    int slot = 0;
    for (int it = 0; it < KT; ++it) {
        // All outstanding cp.async groups complete => image `it` resident.
        asm volatile("cp.async.wait_group 0;" ::: "memory");
        __syncthreads();

        const uint32_t stA = sbase + slot * STAGE2;
        const uint32_t stB = stA + A_IMG;
        const char* nA = gA + (size_t)(it + 1) * A_IMG;
        const char* nB = gB + (size_t)(it + 1) * B_IMG;
        const bool do_refill = (it + 1 < KT);

#pragma unroll
        for (int ks = 0; ks < 4; ks++) {
            const uint32_t kb = (uint32_t)ks << 5;
            uint32_t a[4][4], b[8][2];
#pragma unroll
            for (int i = 0; i < 4; i++) {
                uint32_t ad = stA + (uint32_t)((rA + i * 16) * 128) +
                              ((kb | kgA) ^ sxA);
                LDSM4(a[i][0], a[i][1], a[i][2], a[i][3], ad);
            }
#pragma unroll
            for (int p = 0; p < 4; p++) {
                uint32_t ad = stB + (uint32_t)((rB + p * 16) * 128) +
                              ((kb | kgB) ^ sxB);
                LDSM4(b[2 * p][0], b[2 * p][1], b[2 * p + 1][0],
                      b[2 * p + 1][1], ad);
            }
#pragma unroll
            for (int i = 0; i < 4; i++)
#pragma unroll
                for (int j = 0; j < 8; j++)
                    mma16816(acc[i][j], a[i], b[j]);

            // refill A-next @ks0, B-next @ks1; commit @ks3.
            if (ks == 0) {
                if (do_refill) refA(sbase, slot ^ 1, nA, tid);
            } else if (ks == 1) {
                if (do_refill) refB(sbase, slot ^ 1, nB, tid);
            } else if (ks == 3) {
                CP_COMMIT();   // one group per image (possibly empty)
            }
        }

        slot ^= 1;
    }

    // ---- epilogue: scale by norm reciprocals, write f32 ----
    const int qr = lid >> 2;
    const int qc = (lid & 3) * 2;
    const int mbase = mt * BM + wm * 64;
    const int nbase = nt2 * 128 + wn * 64;
#pragma unroll
    for (int i = 0; i < 4; i++) {
        const int m0 = mbase + i * 16 + qr;
        const float ix0 = g_invx[m0];
        const float ix1 = g_invx[m0 + 8];
        float* row0 = out + (size_t)m0 * N_DIM + nbase;
        float* row1 = row0 + (size_t)8 * N_DIM;
#pragma unroll
        for (int j = 0; j < 8; j++) {
            const int nn = j * 8 + qc;
            const float iw0 = g_invw[nbase + nn];
            const float iw1 = g_invw[nbase + nn + 1];
            float2 v0, v1;
            v0.x = acc[i][j][0] * ix0 * iw0;
            v0.y = acc[i][j][1] * ix0 * iw1;
            v1.x = acc[i][j][2] * ix1 * iw0;
            v1.y = acc[i][j][3] * ix1 * iw1;
            *reinterpret_cast<float2*>(row0 + nn) = v0;
            *reinterpret_cast<float2*>(row1 + nn) = v1;
        }
    }
}

// ---------------------------------------------------------------------------
// kernel_launch
// ---------------------------------------------------------------------------
extern "C" void kernel_launch(void* const* d_in, const int* in_sizes, int n_in,
                              void* d_out, int out_size) {
    (void)in_sizes; (void)n_in; (void)out_size;
    const float* x = (const float*)d_in[0];
    const float* w = (const float*)d_in[1];
    float* out = (float*)d_out;

    cos_conv_x<<<dim3(MT, KT), BM>>>(x);
    cos_conv_w<<<dim3(NT, KT), BN>>>(w);
    cos_norms<<<(M_DIM + N_DIM) / 256, 256>>>();

    cudaFuncSetAttribute(cos_gemm, cudaFuncAttributeMaxDynamicSharedMemorySize,
                         SMEM_G);
    cos_gemm<<<dim3(MT, NT2), 128, SMEM_G>>>(out);
}